// round 10
// baseline (speedup 1.0000x reference)
#include <cuda_runtime.h>
#include <math.h>

typedef unsigned long long u64;

// ---------------- packed f32x2 helpers (sm_103a) ----------------
__device__ __forceinline__ u64 pack2(float a, float b){ u64 r; asm("mov.b64 %0,{%1,%2};":"=l"(r):"f"(a),"f"(b)); return r; }
__device__ __forceinline__ u64 pack1(float a){ u64 r; asm("mov.b64 %0,{%1,%1};":"=l"(r):"f"(a)); return r; }
__device__ __forceinline__ void unpack2(u64 v, float& a, float& b){ asm("mov.b64 {%0,%1},%2;":"=f"(a),"=f"(b):"l"(v)); }
__device__ __forceinline__ u64 fma2(u64 a,u64 b,u64 c){ u64 d; asm("fma.rn.f32x2 %0,%1,%2,%3;":"=l"(d):"l"(a),"l"(b),"l"(c)); return d; }
__device__ __forceinline__ float hadd2(u64 v){ float a,b; unpack2(v,a,b); return a+b; }

// fast tanh via MUFU (EX2 + RCP), rel err ~1e-6
__device__ __forceinline__ float tanh_fast(float x){
    float xc = fminf(fmaxf(x, -10.0f), 10.0f);
    float p = __expf(2.0f * xc);
    return __fdividef(p - 1.0f, p + 1.0f);
}
__device__ __forceinline__ float sig_fast(float x){
    return __fdividef(1.0f, 1.0f + __expf(-x));
}
// tanh-form gelu (verified rel_err ~2e-6 end-to-end)
__device__ __forceinline__ float gelu1(float v){
    float u = v * fmaf(0.044715f * v, v, 1.0f) * 0.7978845608028654f;
    float t = tanh_fast(u);
    return 0.5f * v * (1.0f + t);
}

// ---------------- folded-weight scratch ----------------
__device__ float g_A[1024];   // (wq^T wk) / sqrt(32)
__device__ float g_W1[1024];  // w_ih @ Wo @ wv
__device__ float g_r[32];     // (wk^T bq) / sqrt(32)
__device__ float g_c1[32];    // w_ih @ (Wo bv + bo) + b_ih + b_hh

// ---------------- prep kernel ----------------
__global__ void prep_kernel(const float* __restrict__ ipw, const float* __restrict__ ipb,
                            const float* __restrict__ opw, const float* __restrict__ opb,
                            const float* __restrict__ wih, const float* __restrict__ bih,
                            const float* __restrict__ bhh)
{
    __shared__ float T[1024];
    __shared__ float t2[32];
    const float inv = 0.17677669529663688f;
    int tid = threadIdx.x;
    int i = tid >> 5, j = tid & 31;
    const float* wq = ipw;
    const float* wk = ipw + 1024;
    const float* wv = ipw + 2048;

    float a = 0.f, t = 0.f;
    #pragma unroll 8
    for (int m = 0; m < 32; m++){
        a += wq[m*32 + i] * wk[m*32 + j];
        t += opw[i*32 + m] * wv[m*32 + j];
    }
    g_A[i*32 + j] = a * inv;
    T[i*32 + j] = t;

    if (i == 0){
        float rr = 0.f, tt = 0.f;
        #pragma unroll 8
        for (int m = 0; m < 32; m++){
            rr += ipb[m] * wk[m*32 + j];
            tt += opw[j*32 + m] * ipb[64 + m];
        }
        g_r[j] = rr * inv;
        t2[j] = tt + opb[j];
    }
    __syncthreads();

    float w1 = 0.f;
    #pragma unroll 8
    for (int m = 0; m < 32; m++)
        w1 += wih[i*32 + m] * T[m*32 + j];
    g_W1[i*32 + j] = w1;

    if (i == 0){
        float c = 0.f;
        #pragma unroll 8
        for (int m = 0; m < 32; m++)
            c += wih[j*32 + m] * t2[m];
        g_c1[j] = c + bih[j] + bhh[j];
    }
}

// ---------------- fused main: one row/thread; 160-thr blocks, 2 blocks/SM (cap 204) ----------------
__global__ __launch_bounds__(160, 2) void fused_kernel(
    const float* __restrict__ x,
    const float* __restrict__ embw, const float* __restrict__ embb,
    const float* __restrict__ whh,
    const float* __restrict__ decw, const float* __restrict__ decb,
    const float* __restrict__ outw, const float* __restrict__ outb,
    float* __restrict__ out, int B)
{
    __shared__ __align__(16) float sA [1024];
    __shared__ __align__(16) float sW1[1024];
    __shared__ __align__(16) float sWh[1024];
    __shared__ __align__(16) float sDec[160];
    __shared__ __align__(16) float sR[32];
    __shared__ __align__(16) float sEmbT[160];   // transposed: [k][l]
    __shared__ __align__(16) float sC1[32];
    __shared__ __align__(16) float sEmbB[32];
    __shared__ float sDecB[8];
    __shared__ float sOw[16];
    __shared__ float sOb[4];

    const int tid = threadIdx.x;
    for (int i = tid; i < 1024; i += 160){
        sA[i]  = g_A[i];
        sW1[i] = g_W1[i];
        sWh[i] = whh[i];
    }
    if (tid < 160){
        sDec[tid] = decw[tid];
        int l = tid / 5, k = tid % 5;
        sEmbT[k*32 + l] = embw[tid];
    }
    if (tid < 32){ sC1[tid] = g_c1[tid]; sR[tid] = g_r[tid]; sEmbB[tid] = embb[tid]; }
    if (tid < 15) sOw[tid] = outw[tid];
    if (tid < 5)  sDecB[tid] = decb[tid];
    if (tid < 3)  sOb[tid] = outb[tid];
    __syncthreads();

    int r = blockIdx.x * 160 + tid;
    if (r >= B) return;

    // ---- load x row (10 floats, 8B aligned) ----
    float xv[10];
    {
        const float2* xp = reinterpret_cast<const float2*>(x + (long long)r*10);
        #pragma unroll
        for (int k = 0; k < 5; k++){ float2 t = xp[k]; xv[2*k] = t.x; xv[2*k+1] = t.y; }
    }
    u64 xp0[5], xp1[5];
    #pragma unroll
    for (int k = 0; k < 5; k++){ xp0[k] = pack1(xv[k]); xp1[k] = pack1(xv[5+k]); }

    // ---- embedding (packed along output dims) ----
    u64 e0p[16], dep[16];
    const u64* ebp = reinterpret_cast<const u64*>(sEmbB);
    #pragma unroll
    for (int i = 0; i < 16; i++){
        u64 a0 = ebp[i], a1 = a0;
        #pragma unroll
        for (int k = 0; k < 5; k++){
            u64 w = *reinterpret_cast<const u64*>(sEmbT + k*32 + 2*i);
            a0 = fma2(w, xp0[k], a0);
            a1 = fma2(w, xp1[k], a1);
        }
        float v00, v10, v01, v11;
        unpack2(a0, v00, v10);
        unpack2(a1, v01, v11);
        float g00 = gelu1(v00), g10 = gelu1(v10);
        float g01 = gelu1(v01), g11 = gelu1(v11);
        e0p[i] = pack2(g00, g10);
        dep[i] = pack2(g01 - g00, g11 - g10);
    }

    // ---- attention: delta0 = e0.(A de) + r.de ; delta1 = delta0 + de.(A de) ----
    u64 dE = 0ull, dD = 0ull, dR = 0ull;
    const u64* rp = reinterpret_cast<const u64*>(sR);
    #pragma unroll
    for (int i = 0; i < 16; i++){
        const ulonglong2* rowA0 = reinterpret_cast<const ulonglong2*>(sA + (2*i)*32);
        const ulonglong2* rowA1 = reinterpret_cast<const ulonglong2*>(sA + (2*i+1)*32);
        u64 w0 = 0ull, w1 = 0ull;
        #pragma unroll
        for (int c = 0; c < 8; c++){
            ulonglong2 v0 = rowA0[c], v1 = rowA1[c];
            w0 = fma2(v0.x, dep[2*c],   w0);
            w0 = fma2(v0.y, dep[2*c+1], w0);
            w1 = fma2(v1.x, dep[2*c],   w1);
            w1 = fma2(v1.y, dep[2*c+1], w1);
        }
        u64 wp = pack2(hadd2(w0), hadd2(w1));
        dE = fma2(e0p[i], wp, dE);
        dD = fma2(dep[i], wp, dD);
        dR = fma2(rp[i], dep[i], dR);
    }
    float d0 = hadd2(dE) + hadd2(dR);
    float d1 = d0 + hadd2(dD);
    float a01 = sig_fast(d0);
    float a11 = sig_fast(d1);
    u64 a01p = pack1(a01);
    u64 adp  = pack1(a11 - a01);

    // ---- m0 = e0 + a01*de (in place) ----
    #pragma unroll
    for (int i = 0; i < 16; i++) e0p[i] = fma2(a01p, dep[i], e0p[i]);

    // ---- h1 = tanh(W1 m0 + c1) ----
    u64 h1p[16];
    #pragma unroll
    for (int i = 0; i < 16; i++){
        const ulonglong2* r0w = reinterpret_cast<const ulonglong2*>(sW1 + (2*i)*32);
        const ulonglong2* r1w = reinterpret_cast<const ulonglong2*>(sW1 + (2*i+1)*32);
        u64 s0 = 0ull, s1 = 0ull;
        #pragma unroll
        for (int c = 0; c < 8; c++){
            ulonglong2 v0 = r0w[c], v1 = r1w[c];
            s0 = fma2(v0.x, e0p[2*c],   s0);
            s0 = fma2(v0.y, e0p[2*c+1], s0);
            s1 = fma2(v1.x, e0p[2*c],   s1);
            s1 = fma2(v1.y, e0p[2*c+1], s1);
        }
        float v0 = hadd2(s0) + sC1[2*i];
        float v1 = hadd2(s1) + sC1[2*i+1];
        h1p[i] = pack2(tanh_fast(v0), tanh_fast(v1));
    }

    // ---- m1 = m0 + (a11-a01)*de (in place) ----
    #pragma unroll
    for (int i = 0; i < 16; i++) e0p[i] = fma2(adp, dep[i], e0p[i]);

    // ---- h2 = tanh(W1 m1 + Wh h1 + c1); write into dep (register reuse) ----
    #pragma unroll
    for (int i = 0; i < 16; i++){
        const ulonglong2* rw0 = reinterpret_cast<const ulonglong2*>(sW1 + (2*i)*32);
        const ulonglong2* rw1 = reinterpret_cast<const ulonglong2*>(sW1 + (2*i+1)*32);
        const ulonglong2* rh0 = reinterpret_cast<const ulonglong2*>(sWh + (2*i)*32);
        const ulonglong2* rh1 = reinterpret_cast<const ulonglong2*>(sWh + (2*i+1)*32);
        u64 s0 = 0ull, s1 = 0ull, t0 = 0ull, t1 = 0ull;
        #pragma unroll
        for (int c = 0; c < 8; c++){
            ulonglong2 vw0 = rw0[c], vh0 = rh0[c];
            ulonglong2 vw1 = rw1[c], vh1 = rh1[c];
            s0 = fma2(vw0.x, e0p[2*c],   s0);
            s0 = fma2(vw0.y, e0p[2*c+1], s0);
            t0 = fma2(vh0.x, h1p[2*c],   t0);
            t0 = fma2(vh0.y, h1p[2*c+1], t0);
            s1 = fma2(vw1.x, e0p[2*c],   s1);
            s1 = fma2(vw1.y, e0p[2*c+1], s1);
            t1 = fma2(vh1.x, h1p[2*c],   t1);
            t1 = fma2(vh1.y, h1p[2*c+1], t1);
        }
        float v0 = hadd2(s0) + hadd2(t0) + sC1[2*i];
        float v1 = hadd2(s1) + hadd2(t1) + sC1[2*i+1];
        dep[i] = pack2(tanh_fast(v0), tanh_fast(v1));   // h2 -> dep
    }

    // ---- decode: d = gelu(Dec h2 + b) ; out = Ow d + ob ----
    float dv[5];
    #pragma unroll
    for (int j = 0; j < 5; j++){
        const ulonglong2* rd = reinterpret_cast<const ulonglong2*>(sDec + j*32);
        u64 acc = 0ull;
        #pragma unroll
        for (int c = 0; c < 8; c++){
            ulonglong2 v = rd[c];
            acc = fma2(v.x, dep[2*c],   acc);
            acc = fma2(v.y, dep[2*c+1], acc);
        }
        dv[j] = gelu1(hadd2(acc) + sDecB[j]);
    }
    #pragma unroll
    for (int o = 0; o < 3; o++){
        float acc = sOb[o];
        #pragma unroll
        for (int j = 0; j < 5; j++) acc = fmaf(sOw[o*5 + j], dv[j], acc);
        out[(long long)r*3 + o] = acc;
    }
}

// ---------------- launch ----------------
extern "C" void kernel_launch(void* const* d_in, const int* in_sizes, int n_in,
                              void* d_out, int out_size)
{
    const float* x      = (const float*)d_in[0];
    const float* embw   = (const float*)d_in[1];
    const float* embb   = (const float*)d_in[2];
    const float* ipw    = (const float*)d_in[3];
    const float* ipb    = (const float*)d_in[4];
    const float* opw    = (const float*)d_in[5];
    const float* opb    = (const float*)d_in[6];
    const float* wih    = (const float*)d_in[7];
    const float* bih    = (const float*)d_in[8];
    const float* whh    = (const float*)d_in[9];
    const float* bhh    = (const float*)d_in[10];
    const float* decw   = (const float*)d_in[11];
    const float* decb   = (const float*)d_in[12];
    const float* outw   = (const float*)d_in[13];
    const float* outb   = (const float*)d_in[14];
    float* out = (float*)d_out;

    int B = in_sizes[0] / 10;

    prep_kernel<<<1, 1024>>>(ipw, ipb, opw, opb, wih, bih, bhh);

    int blocks = (B + 159) / 160;
    fused_kernel<<<blocks, 160>>>(x, embw, embb, whh, decw, decb, outw, outb, out, B);
}

// round 11
// speedup vs baseline: 1.7881x; 1.7881x over previous
#include <cuda_runtime.h>
#include <math.h>

typedef unsigned long long u64;

// ---------------- packed f32x2 helpers (sm_103a) ----------------
__device__ __forceinline__ u64 pack2(float a, float b){ u64 r; asm("mov.b64 %0,{%1,%2};":"=l"(r):"f"(a),"f"(b)); return r; }
__device__ __forceinline__ u64 pack1(float a){ u64 r; asm("mov.b64 %0,{%1,%1};":"=l"(r):"f"(a)); return r; }
__device__ __forceinline__ void unpack2(u64 v, float& a, float& b){ asm("mov.b64 {%0,%1},%2;":"=f"(a),"=f"(b):"l"(v)); }
__device__ __forceinline__ u64 fma2(u64 a,u64 b,u64 c){ u64 d; asm("fma.rn.f32x2 %0,%1,%2,%3;":"=l"(d):"l"(a),"l"(b),"l"(c)); return d; }
__device__ __forceinline__ float hadd2(u64 v){ float a,b; unpack2(v,a,b); return a+b; }

// HW tanh (MUFU.TANH, sm_75+): 1 instruction, rel err ~2^-11
__device__ __forceinline__ float tanh_hw(float x){
    float y; asm("tanh.approx.f32 %0, %1;" : "=f"(y) : "f"(x)); return y;
}
__device__ __forceinline__ float sig_hw(float x){
    return fmaf(0.5f, tanh_hw(0.5f * x), 0.5f);
}
// tanh-form gelu with HW tanh; error ~0.5|v|*5e-4, tiny in our |v|<1 regime
__device__ __forceinline__ float gelu1(float v){
    float u = (v * 0.7978845608028654f) * fmaf(0.044715f * v, v, 1.0f);
    float hv = 0.5f * v;
    return fmaf(hv, tanh_hw(u), hv);
}

// ---------------- folded-weight scratch ----------------
__device__ float g_A[1024];   // (wq^T wk) / sqrt(32)
__device__ float g_W1[1024];  // w_ih @ Wo @ wv
__device__ float g_r[32];     // (wk^T bq) / sqrt(32)
__device__ float g_c1[32];    // w_ih @ (Wo bv + bo) + b_ih + b_hh

// ---------------- prep kernel ----------------
__global__ void prep_kernel(const float* __restrict__ ipw, const float* __restrict__ ipb,
                            const float* __restrict__ opw, const float* __restrict__ opb,
                            const float* __restrict__ wih, const float* __restrict__ bih,
                            const float* __restrict__ bhh)
{
    __shared__ float T[1024];
    __shared__ float t2[32];
    const float inv = 0.17677669529663688f;
    int tid = threadIdx.x;
    int i = tid >> 5, j = tid & 31;
    const float* wq = ipw;
    const float* wk = ipw + 1024;
    const float* wv = ipw + 2048;

    float a = 0.f, t = 0.f;
    #pragma unroll 8
    for (int m = 0; m < 32; m++){
        a += wq[m*32 + i] * wk[m*32 + j];
        t += opw[i*32 + m] * wv[m*32 + j];
    }
    g_A[i*32 + j] = a * inv;
    T[i*32 + j] = t;

    if (i == 0){
        float rr = 0.f, tt = 0.f;
        #pragma unroll 8
        for (int m = 0; m < 32; m++){
            rr += ipb[m] * wk[m*32 + j];
            tt += opw[j*32 + m] * ipb[64 + m];
        }
        g_r[j] = rr * inv;
        t2[j] = tt + opb[j];
    }
    __syncthreads();

    float w1 = 0.f;
    #pragma unroll 8
    for (int m = 0; m < 32; m++)
        w1 += wih[i*32 + m] * T[m*32 + j];
    g_W1[i*32 + j] = w1;

    if (i == 0){
        float c = 0.f;
        #pragma unroll 8
        for (int m = 0; m < 32; m++)
            c += wih[j*32 + m] * t2[m];
        g_c1[j] = c + bih[j] + bhh[j];
    }
}

// ---------------- fused main: one row/thread, 256-thr blocks, NO reg cap ----------------
__global__ __launch_bounds__(256) void fused_kernel(
    const float* __restrict__ x,
    const float* __restrict__ embw, const float* __restrict__ embb,
    const float* __restrict__ whh,
    const float* __restrict__ decw, const float* __restrict__ decb,
    const float* __restrict__ outw, const float* __restrict__ outb,
    float* __restrict__ out, int B)
{
    __shared__ __align__(16) float sA [1024];
    __shared__ __align__(16) float sW1[1024];
    __shared__ __align__(16) float sWh[1024];
    __shared__ __align__(16) float sDec[160];
    __shared__ __align__(16) float sR[32];
    __shared__ __align__(16) float sEmbT[160];   // transposed: [k][l]
    __shared__ __align__(16) float sC1[32];
    __shared__ __align__(16) float sEmbB[32];
    __shared__ float sDecB[8];
    __shared__ float sOw[16];
    __shared__ float sOb[4];

    const int tid = threadIdx.x;
    for (int i = tid; i < 1024; i += 256){
        sA[i]  = g_A[i];
        sW1[i] = g_W1[i];
        sWh[i] = whh[i];
    }
    if (tid < 160){
        sDec[tid] = decw[tid];
        int l = tid / 5, k = tid % 5;
        sEmbT[k*32 + l] = embw[tid];
    }
    if (tid < 32){ sC1[tid] = g_c1[tid]; sR[tid] = g_r[tid]; sEmbB[tid] = embb[tid]; }
    if (tid < 15) sOw[tid] = outw[tid];
    if (tid < 5)  sDecB[tid] = decb[tid];
    if (tid < 3)  sOb[tid] = outb[tid];
    __syncthreads();

    int r = blockIdx.x * 256 + tid;
    if (r >= B) return;

    // ---- load x row (10 floats, 8B aligned) ----
    float xv[10];
    {
        const float2* xp = reinterpret_cast<const float2*>(x + (long long)r*10);
        #pragma unroll
        for (int k = 0; k < 5; k++){ float2 t = xp[k]; xv[2*k] = t.x; xv[2*k+1] = t.y; }
    }
    u64 xp0[5], xp1[5];
    #pragma unroll
    for (int k = 0; k < 5; k++){ xp0[k] = pack1(xv[k]); xp1[k] = pack1(xv[5+k]); }

    // ---- embedding (packed along output dims) ----
    u64 e0p[16], dep[16];
    const u64* ebp = reinterpret_cast<const u64*>(sEmbB);
    #pragma unroll
    for (int i = 0; i < 16; i++){
        u64 a0 = ebp[i], a1 = a0;
        #pragma unroll
        for (int k = 0; k < 5; k++){
            u64 w = *reinterpret_cast<const u64*>(sEmbT + k*32 + 2*i);
            a0 = fma2(w, xp0[k], a0);
            a1 = fma2(w, xp1[k], a1);
        }
        float v00, v10, v01, v11;
        unpack2(a0, v00, v10);
        unpack2(a1, v01, v11);
        float g00 = gelu1(v00), g10 = gelu1(v10);
        float g01 = gelu1(v01), g11 = gelu1(v11);
        e0p[i] = pack2(g00, g10);
        dep[i] = pack2(g01 - g00, g11 - g10);
    }

    // ---- attention: delta0 = e0.(A de) + r.de ; delta1 = delta0 + de.(A de) ----
    u64 dE = 0ull, dD = 0ull, dR = 0ull;
    const u64* rp = reinterpret_cast<const u64*>(sR);
    #pragma unroll
    for (int i = 0; i < 16; i++){
        const ulonglong2* rowA0 = reinterpret_cast<const ulonglong2*>(sA + (2*i)*32);
        const ulonglong2* rowA1 = reinterpret_cast<const ulonglong2*>(sA + (2*i+1)*32);
        u64 w0 = 0ull, w1 = 0ull;
        #pragma unroll
        for (int c = 0; c < 8; c++){
            ulonglong2 v0 = rowA0[c], v1 = rowA1[c];
            w0 = fma2(v0.x, dep[2*c],   w0);
            w0 = fma2(v0.y, dep[2*c+1], w0);
            w1 = fma2(v1.x, dep[2*c],   w1);
            w1 = fma2(v1.y, dep[2*c+1], w1);
        }
        u64 wp = pack2(hadd2(w0), hadd2(w1));
        dE = fma2(e0p[i], wp, dE);
        dD = fma2(dep[i], wp, dD);
        dR = fma2(rp[i], dep[i], dR);
    }
    float d0 = hadd2(dE) + hadd2(dR);
    float d1 = d0 + hadd2(dD);
    float a01 = sig_hw(d0);
    float a11 = sig_hw(d1);
    u64 a01p = pack1(a01);
    u64 adp  = pack1(a11 - a01);

    // ---- m0 = e0 + a01*de (in place) ----
    #pragma unroll
    for (int i = 0; i < 16; i++) e0p[i] = fma2(a01p, dep[i], e0p[i]);

    // ---- h1 = tanh(W1 m0 + c1) ----
    u64 h1p[16];
    #pragma unroll
    for (int i = 0; i < 16; i++){
        const ulonglong2* r0w = reinterpret_cast<const ulonglong2*>(sW1 + (2*i)*32);
        const ulonglong2* r1w = reinterpret_cast<const ulonglong2*>(sW1 + (2*i+1)*32);
        u64 s0 = 0ull, s1 = 0ull;
        #pragma unroll
        for (int c = 0; c < 8; c++){
            ulonglong2 v0 = r0w[c], v1 = r1w[c];
            s0 = fma2(v0.x, e0p[2*c],   s0);
            s0 = fma2(v0.y, e0p[2*c+1], s0);
            s1 = fma2(v1.x, e0p[2*c],   s1);
            s1 = fma2(v1.y, e0p[2*c+1], s1);
        }
        float v0 = hadd2(s0) + sC1[2*i];
        float v1 = hadd2(s1) + sC1[2*i+1];
        h1p[i] = pack2(tanh_hw(v0), tanh_hw(v1));
    }

    // ---- m1 = m0 + (a11-a01)*de (in place) ----
    #pragma unroll
    for (int i = 0; i < 16; i++) e0p[i] = fma2(adp, dep[i], e0p[i]);

    // ---- h2 = tanh(W1 m1 + Wh h1 + c1); write into dep (register reuse) ----
    #pragma unroll
    for (int i = 0; i < 16; i++){
        const ulonglong2* rw0 = reinterpret_cast<const ulonglong2*>(sW1 + (2*i)*32);
        const ulonglong2* rw1 = reinterpret_cast<const ulonglong2*>(sW1 + (2*i+1)*32);
        const ulonglong2* rh0 = reinterpret_cast<const ulonglong2*>(sWh + (2*i)*32);
        const ulonglong2* rh1 = reinterpret_cast<const ulonglong2*>(sWh + (2*i+1)*32);
        u64 s0 = 0ull, s1 = 0ull, t0 = 0ull, t1 = 0ull;
        #pragma unroll
        for (int c = 0; c < 8; c++){
            ulonglong2 vw0 = rw0[c], vh0 = rh0[c];
            ulonglong2 vw1 = rw1[c], vh1 = rh1[c];
            s0 = fma2(vw0.x, e0p[2*c],   s0);
            s0 = fma2(vw0.y, e0p[2*c+1], s0);
            t0 = fma2(vh0.x, h1p[2*c],   t0);
            t0 = fma2(vh0.y, h1p[2*c+1], t0);
            s1 = fma2(vw1.x, e0p[2*c],   s1);
            s1 = fma2(vw1.y, e0p[2*c+1], s1);
            t1 = fma2(vh1.x, h1p[2*c],   t1);
            t1 = fma2(vh1.y, h1p[2*c+1], t1);
        }
        float v0 = hadd2(s0) + hadd2(t0) + sC1[2*i];
        float v1 = hadd2(s1) + hadd2(t1) + sC1[2*i+1];
        dep[i] = pack2(tanh_hw(v0), tanh_hw(v1));   // h2 -> dep
    }

    // ---- decode: d = gelu(Dec h2 + b) ; out = Ow d + ob ----
    float dv[5];
    #pragma unroll
    for (int j = 0; j < 5; j++){
        const ulonglong2* rd = reinterpret_cast<const ulonglong2*>(sDec + j*32);
        u64 acc = 0ull;
        #pragma unroll
        for (int c = 0; c < 8; c++){
            ulonglong2 v = rd[c];
            acc = fma2(v.x, dep[2*c],   acc);
            acc = fma2(v.y, dep[2*c+1], acc);
        }
        dv[j] = gelu1(hadd2(acc) + sDecB[j]);
    }
    #pragma unroll
    for (int o = 0; o < 3; o++){
        float acc = sOb[o];
        #pragma unroll
        for (int j = 0; j < 5; j++) acc = fmaf(sOw[o*5 + j], dv[j], acc);
        out[(long long)r*3 + o] = acc;
    }
}

// ---------------- launch ----------------
extern "C" void kernel_launch(void* const* d_in, const int* in_sizes, int n_in,
                              void* d_out, int out_size)
{
    const float* x      = (const float*)d_in[0];
    const float* embw   = (const float*)d_in[1];
    const float* embb   = (const float*)d_in[2];
    const float* ipw    = (const float*)d_in[3];
    const float* ipb    = (const float*)d_in[4];
    const float* opw    = (const float*)d_in[5];
    const float* opb    = (const float*)d_in[6];
    const float* wih    = (const float*)d_in[7];
    const float* bih    = (const float*)d_in[8];
    const float* whh    = (const float*)d_in[9];
    const float* bhh    = (const float*)d_in[10];
    const float* decw   = (const float*)d_in[11];
    const float* decb   = (const float*)d_in[12];
    const float* outw   = (const float*)d_in[13];
    const float* outb   = (const float*)d_in[14];
    float* out = (float*)d_out;

    int B = in_sizes[0] / 10;

    prep_kernel<<<1, 1024>>>(ipw, ipb, opw, opb, wih, bih, bhh);

    int blocks = (B + 255) / 256;
    fused_kernel<<<blocks, 256>>>(x, embw, embb, whh, decw, decb, outw, outb, out, B);
}